// round 3
// baseline (speedup 1.0000x reference)
#include <cuda_runtime.h>
#include <cuda_bf16.h>
#include <cstdint>

// ---------------------------------------------------------------------------
// GCN VGAE encoder:
//   deg[i] = indeg(i)+1 ; dinv = rsqrt(deg)
//   conv(X,W,b): hs = (X@W)*dinv[row]; agg = hs (self) + scatter_add(hs[src]->dst)
//                out = relu(dinv[row]*agg + b)
//   mu = H@Wmu + bmu ; logvar = H@Wlv + blv   (fused 128-col GEMM)
// edge_index arrives as int32. All scratch buffers are __device__ globals and
// are ONLY referenced from device code (host-side __device__ symbol use is UB;
// on GB300/ATS it silently reads host memory -> zeros).
// ---------------------------------------------------------------------------

#define MAXN 50000
#define FDIM 128

__device__ float g_dinv[MAXN];
__device__ float g_hs [MAXN * FDIM];
__device__ float g_agg[MAXN * FDIM];
__device__ float g_h  [MAXN * FDIM];

// ---------------- degree / dinv ----------------

__global__ void init_one_kernel(int N) {
    int i = blockIdx.x * blockDim.x + threadIdx.x;
    if (i < N) g_dinv[i] = 1.0f;
}

__global__ void count_deg_kernel(const int* __restrict__ ei, int E) {
    int e = blockIdx.x * blockDim.x + threadIdx.x;
    if (e < E) {
        int d = ei[E + e];
        atomicAdd(&g_dinv[d], 1.0f);
    }
}

__global__ void rsqrt_kernel(int N) {
    int i = blockIdx.x * blockDim.x + threadIdx.x;
    if (i < N) g_dinv[i] = rsqrtf(g_dinv[i]);
}

// ---------------- GEMM (conv): hs = (X@W)*dinv, agg = hs ----------------
// 256 threads, 32 rows x 128 cols per block. W[128][128] + Xs[32][128] in smem.
// src==0: read from xin (harness input). src==1: read from g_h (device global).

#define GEMM_SMEM ((128 * 128 + 32 * 128) * 4)

__global__ void gemm_conv_kernel(const float* __restrict__ xin,
                                 const float* __restrict__ W,
                                 int N, int src) {
    extern __shared__ float sm[];
    float* Ws = sm;                 // [128][128]
    float* Xs = sm + 128 * 128;     // [32][128]
    const int t = threadIdx.x;
    const float* X = (src == 0) ? xin : (const float*)g_h;

    // load W (4096 float4)
#pragma unroll
    for (int i = 0; i < 16; i++) {
        int idx = t + i * 256;
        ((float4*)Ws)[idx] = ((const float4*)W)[idx];
    }
    const int rowBase = blockIdx.x * 32;
    // load X tile (1024 float4), rows zeroed past N
#pragma unroll
    for (int i = 0; i < 4; i++) {
        int idx = t + i * 256;
        int r = idx >> 5;
        int rg = rowBase + r;
        float4 v = make_float4(0.f, 0.f, 0.f, 0.f);
        if (rg < N) v = ((const float4*)X)[(size_t)rg * 32 + (idx & 31)];
        ((float4*)Xs)[idx] = v;
    }
    __syncthreads();

    const int tx = t & 31, ty = t >> 5;
    const int c0 = tx * 4;
    const int r0 = ty * 4;
    float acc[4][4];
#pragma unroll
    for (int i = 0; i < 4; i++)
#pragma unroll
        for (int j = 0; j < 4; j++) acc[i][j] = 0.f;

#pragma unroll 8
    for (int k = 0; k < 128; k++) {
        float4 wv = *(const float4*)(Ws + k * 128 + c0);
        float x0 = Xs[(r0 + 0) * 128 + k];
        float x1 = Xs[(r0 + 1) * 128 + k];
        float x2 = Xs[(r0 + 2) * 128 + k];
        float x3 = Xs[(r0 + 3) * 128 + k];
        acc[0][0] += x0 * wv.x; acc[0][1] += x0 * wv.y; acc[0][2] += x0 * wv.z; acc[0][3] += x0 * wv.w;
        acc[1][0] += x1 * wv.x; acc[1][1] += x1 * wv.y; acc[1][2] += x1 * wv.z; acc[1][3] += x1 * wv.w;
        acc[2][0] += x2 * wv.x; acc[2][1] += x2 * wv.y; acc[2][2] += x2 * wv.z; acc[2][3] += x2 * wv.w;
        acc[3][0] += x3 * wv.x; acc[3][1] += x3 * wv.y; acc[3][2] += x3 * wv.z; acc[3][3] += x3 * wv.w;
    }

#pragma unroll
    for (int i = 0; i < 4; i++) {
        int r = rowBase + r0 + i;
        if (r < N) {
            float dv = g_dinv[r];
            float4 o = make_float4(acc[i][0] * dv, acc[i][1] * dv, acc[i][2] * dv, acc[i][3] * dv);
            *(float4*)(g_hs  + (size_t)r * 128 + c0) = o;
            *(float4*)(g_agg + (size_t)r * 128 + c0) = o;   // self-loop term pre-seeded
        }
    }
}

// ---------------- GEMM (final): [mu | logvar] = H @ [Wmu|Wlv] + [bmu|blv] ----

__global__ void gemm_final_kernel(const float* __restrict__ Wmu,
                                  const float* __restrict__ Wlv,
                                  const float* __restrict__ bmu,
                                  const float* __restrict__ blv,
                                  float* __restrict__ out,
                                  int N) {
    extern __shared__ float sm[];
    float* Ws = sm;                 // [128][128] : cols 0-63 = Wmu, 64-127 = Wlv
    float* Xs = sm + 128 * 128;     // [32][128]
    const int t = threadIdx.x;

#pragma unroll
    for (int i = 0; i < 16; i++) {
        int idx = t + i * 256;
        int k = idx >> 5;
        int cc4 = idx & 31;  // float4 column within the 128-wide fused W
        float4 v = (cc4 < 16) ? ((const float4*)Wmu)[k * 16 + cc4]
                              : ((const float4*)Wlv)[k * 16 + (cc4 - 16)];
        ((float4*)Ws)[idx] = v;
    }
    const int rowBase = blockIdx.x * 32;
#pragma unroll
    for (int i = 0; i < 4; i++) {
        int idx = t + i * 256;
        int r = idx >> 5;
        int rg = rowBase + r;
        float4 v = make_float4(0.f, 0.f, 0.f, 0.f);
        if (rg < N) v = ((const float4*)g_h)[(size_t)rg * 32 + (idx & 31)];
        ((float4*)Xs)[idx] = v;
    }
    __syncthreads();

    const int tx = t & 31, ty = t >> 5;
    const int c0 = tx * 4;
    const int r0 = ty * 4;
    float acc[4][4];
#pragma unroll
    for (int i = 0; i < 4; i++)
#pragma unroll
        for (int j = 0; j < 4; j++) acc[i][j] = 0.f;

#pragma unroll 8
    for (int k = 0; k < 128; k++) {
        float4 wv = *(const float4*)(Ws + k * 128 + c0);
        float x0 = Xs[(r0 + 0) * 128 + k];
        float x1 = Xs[(r0 + 1) * 128 + k];
        float x2 = Xs[(r0 + 2) * 128 + k];
        float x3 = Xs[(r0 + 3) * 128 + k];
        acc[0][0] += x0 * wv.x; acc[0][1] += x0 * wv.y; acc[0][2] += x0 * wv.z; acc[0][3] += x0 * wv.w;
        acc[1][0] += x1 * wv.x; acc[1][1] += x1 * wv.y; acc[1][2] += x1 * wv.z; acc[1][3] += x1 * wv.w;
        acc[2][0] += x2 * wv.x; acc[2][1] += x2 * wv.y; acc[2][2] += x2 * wv.z; acc[2][3] += x2 * wv.w;
        acc[3][0] += x3 * wv.x; acc[3][1] += x3 * wv.y; acc[3][2] += x3 * wv.z; acc[3][3] += x3 * wv.w;
    }

    const bool is_mu = (c0 < 64);
    float4 bias = is_mu ? *(const float4*)(bmu + c0) : *(const float4*)(blv + (c0 - 64));
#pragma unroll
    for (int i = 0; i < 4; i++) {
        int r = rowBase + r0 + i;
        if (r < N) {
            float4 o = make_float4(acc[i][0] + bias.x, acc[i][1] + bias.y,
                                   acc[i][2] + bias.z, acc[i][3] + bias.w);
            if (is_mu)
                *(float4*)(out + (size_t)r * 64 + c0) = o;
            else
                *(float4*)(out + (size_t)N * 64 + (size_t)r * 64 + (c0 - 64)) = o;
        }
    }
}

// ---------------- scatter: agg[dst] += hs[src] (one warp per edge) ----------

__device__ __forceinline__ void red_add_v4(float* p, float4 v) {
    asm volatile("red.global.add.v4.f32 [%0], {%1, %2, %3, %4};"
                 :: "l"(p), "f"(v.x), "f"(v.y), "f"(v.z), "f"(v.w)
                 : "memory");
}

__global__ void scatter_kernel(const int* __restrict__ ei, int E) {
    int w = (blockIdx.x * blockDim.x + threadIdx.x) >> 5;
    int lane = threadIdx.x & 31;
    if (w >= E) return;
    int s = ei[w];
    int d = ei[E + w];
    float4 v = *(const float4*)(g_hs + (size_t)s * 128 + lane * 4);
    red_add_v4(g_agg + (size_t)d * 128 + lane * 4, v);
}

// ---------------- finalize: H = relu(dinv*agg + b) ----------------

__global__ void finalize_kernel(const float* __restrict__ b, int N) {
    long long idx = (long long)blockIdx.x * blockDim.x + threadIdx.x; // over N*32 float4
    if (idx >= (long long)N * 32) return;
    int r = (int)(idx >> 5);
    int c = (int)(idx & 31) * 4;
    float dv = g_dinv[r];
    float4 a = ((const float4*)g_agg)[idx];
    float4 bb = *(const float4*)(b + c);
    float4 o;
    o.x = fmaxf(a.x * dv + bb.x, 0.f);
    o.y = fmaxf(a.y * dv + bb.y, 0.f);
    o.z = fmaxf(a.z * dv + bb.z, 0.f);
    o.w = fmaxf(a.w * dv + bb.w, 0.f);
    ((float4*)g_h)[idx] = o;
}

// ---------------- launch ----------------

extern "C" void kernel_launch(void* const* d_in, const int* in_sizes, int n_in,
                              void* d_out, int out_size) {
    const float* x   = (const float*)d_in[0];
    const int*   ei  = (const int*)d_in[1];      // int32 edge_index [2, E]
    const float* W1  = (const float*)d_in[2];
    const float* b1  = (const float*)d_in[3];
    const float* W2  = (const float*)d_in[4];
    const float* b2  = (const float*)d_in[5];
    const float* Wmu = (const float*)d_in[6];
    const float* bmu = (const float*)d_in[7];
    const float* Wlv = (const float*)d_in[8];
    const float* blv = (const float*)d_in[9];
    float* out = (float*)d_out;

    const int N = in_sizes[0] / 128;
    const int E = in_sizes[1] / 2;

    cudaFuncSetAttribute(gemm_conv_kernel,
                         cudaFuncAttributeMaxDynamicSharedMemorySize, GEMM_SMEM);
    cudaFuncSetAttribute(gemm_final_kernel,
                         cudaFuncAttributeMaxDynamicSharedMemorySize, GEMM_SMEM);

    const int gemm_blocks = (N + 31) / 32;
    const int scat_blocks = (E + 7) / 8;              // 8 warps/block, 1 warp/edge
    const int fin_blocks  = (int)(((long long)N * 32 + 255) / 256);

    // degrees
    init_one_kernel<<<(N + 255) / 256, 256>>>(N);
    count_deg_kernel<<<(E + 255) / 256, 256>>>(ei, E);
    rsqrt_kernel<<<(N + 255) / 256, 256>>>(N);

    // conv1 (reads harness input x)
    gemm_conv_kernel<<<gemm_blocks, 256, GEMM_SMEM>>>(x, W1, N, 0);
    scatter_kernel<<<scat_blocks, 256>>>(ei, E);
    finalize_kernel<<<fin_blocks, 256>>>(b1, N);

    // conv2 (reads g_h via device-side pointer)
    gemm_conv_kernel<<<gemm_blocks, 256, GEMM_SMEM>>>(x, W2, N, 1);
    scatter_kernel<<<scat_blocks, 256>>>(ei, E);
    finalize_kernel<<<fin_blocks, 256>>>(b2, N);

    // heads
    gemm_final_kernel<<<gemm_blocks, 256, GEMM_SMEM>>>(Wmu, Wlv, bmu, blv, out, N);
}

// round 4
// speedup vs baseline: 1.1099x; 1.1099x over previous
#include <cuda_runtime.h>
#include <cuda_bf16.h>
#include <cstdint>

// ---------------------------------------------------------------------------
// GCN VGAE encoder (fp32, f32x2-packed FFMA GEMMs, fused epilogues):
//   dinv = rsqrt(indeg+1)
//   conv: hs = (X@W)*dinv[row]; agg = hs (self-loop seed) + scatter(hs[src]->dst)
//         next-layer input = relu(dinv[row]*agg + b)   <-- fused into consumer GEMM
//   heads: [mu|lv] = relu(dinv*aggB + b2) @ [Wmu|Wlv] + bias
// Scratch = __device__ globals, referenced ONLY from device code.
// ---------------------------------------------------------------------------

#define MAXN 50000
#define FDIM 128

__device__ float g_dinv[MAXN];
__device__ float g_hs  [MAXN * FDIM];
__device__ float g_aggA[MAXN * FDIM];
__device__ float g_aggB[MAXN * FDIM];

// ---- f32x2 helpers (exact fp32 lanes, double-rate) ----
#define SPLAT2(d, x) asm("mov.b64 %0, {%1, %1};" : "=l"(d) : "f"(x))
#define FMA2(d, a, b, c) \
    asm("fma.rn.f32x2 %0, %1, %2, %3;" : "=l"(d) : "l"(a), "l"(b), "l"(c))
#define UNPACK2(lo, hi, v) \
    asm("mov.b64 {%0, %1}, %2;" : "=f"(lo), "=f"(hi) : "l"(v))

// ---------------- degree / dinv ----------------

__global__ void init_one_kernel(int N) {
    int i = blockIdx.x * blockDim.x + threadIdx.x;
    if (i < N) g_dinv[i] = 1.0f;
}

__global__ void count_deg_kernel(const int* __restrict__ ei, int E) {
    int e = blockIdx.x * blockDim.x + threadIdx.x;
    if (e < E) atomicAdd(&g_dinv[ei[E + e]], 1.0f);
}

__global__ void rsqrt_kernel(int N) {
    int i = blockIdx.x * blockDim.x + threadIdx.x;
    if (i < N) g_dinv[i] = rsqrtf(g_dinv[i]);
}

// ---------------- shared GEMM machinery ----------------
// 256 threads, tile 32 rows x 128 cols. Ws[128][128] + Xs[32][128] in smem.
// Thread (tx,ty): cols tx*4..+3 (2 f32x2 pairs), rows ty*4..+3.

#define GEMM_SMEM ((128 * 128 + 32 * 128) * 4)

// Stage X tile into smem; optionally fuse relu(dinv*v + bias).
__device__ __forceinline__ void load_xtile(float* Xs, const float* __restrict__ src,
                                           const float* __restrict__ bias, int fuse,
                                           int rowBase, int N, int t) {
#pragma unroll
    for (int i = 0; i < 4; i++) {
        int idx = t + i * 256;
        int r = idx >> 5, c4 = idx & 31;
        int rg = rowBase + r;
        float4 v = make_float4(0.f, 0.f, 0.f, 0.f);
        if (rg < N) {
            v = ((const float4*)src)[(size_t)rg * 32 + c4];
            if (fuse) {
                float dv = g_dinv[rg];
                float4 bb = ((const float4*)bias)[c4];
                v.x = fmaxf(v.x * dv + bb.x, 0.f);
                v.y = fmaxf(v.y * dv + bb.y, 0.f);
                v.z = fmaxf(v.z * dv + bb.z, 0.f);
                v.w = fmaxf(v.w * dv + bb.w, 0.f);
            }
        }
        ((float4*)Xs)[idx] = v;
    }
}

// Core 32x128x128 tile product with f32x2 accumulators.
__device__ __forceinline__ void mm_tile(const float* Ws, const float* Xs,
                                        int c0, int r0,
                                        unsigned long long acc[4][2]) {
#pragma unroll
    for (int i = 0; i < 4; i++) { acc[i][0] = 0ull; acc[i][1] = 0ull; }
#pragma unroll 4
    for (int k = 0; k < 128; k += 4) {
        ulonglong2 w0 = *(const ulonglong2*)(Ws + (k + 0) * 128 + c0);
        ulonglong2 w1 = *(const ulonglong2*)(Ws + (k + 1) * 128 + c0);
        ulonglong2 w2 = *(const ulonglong2*)(Ws + (k + 2) * 128 + c0);
        ulonglong2 w3 = *(const ulonglong2*)(Ws + (k + 3) * 128 + c0);
#pragma unroll
        for (int i = 0; i < 4; i++) {
            float4 xv = *(const float4*)(Xs + (r0 + i) * 128 + k);
            unsigned long long s;
            SPLAT2(s, xv.x);
            FMA2(acc[i][0], s, w0.x, acc[i][0]); FMA2(acc[i][1], s, w0.y, acc[i][1]);
            SPLAT2(s, xv.y);
            FMA2(acc[i][0], s, w1.x, acc[i][0]); FMA2(acc[i][1], s, w1.y, acc[i][1]);
            SPLAT2(s, xv.z);
            FMA2(acc[i][0], s, w2.x, acc[i][0]); FMA2(acc[i][1], s, w2.y, acc[i][1]);
            SPLAT2(s, xv.w);
            FMA2(acc[i][0], s, w3.x, acc[i][0]); FMA2(acc[i][1], s, w3.y, acc[i][1]);
        }
    }
}

// ---------------- conv GEMM: hs = (X@W)*dinv ; agg seeded = hs -------------
// stage 0: X = xin (raw), agg out = g_aggA
// stage 1: X = relu(dinv*g_aggA + bias), agg out = g_aggB

__global__ void __launch_bounds__(256)
gemm_conv_kernel(const float* __restrict__ xin,
                 const float* __restrict__ W,
                 const float* __restrict__ bias,
                 int N, int stage) {
    extern __shared__ float sm[];
    float* Ws = sm;
    float* Xs = sm + 128 * 128;
    const int t = threadIdx.x;

    const float* src = (stage == 0) ? xin : (const float*)g_aggA;
    float* aggout = (stage == 0) ? g_aggA : g_aggB;

#pragma unroll
    for (int i = 0; i < 16; i++) {
        int idx = t + i * 256;
        ((float4*)Ws)[idx] = ((const float4*)W)[idx];
    }
    const int rowBase = blockIdx.x * 32;
    load_xtile(Xs, src, bias, stage != 0, rowBase, N, t);
    __syncthreads();

    const int tx = t & 31, ty = t >> 5;
    const int c0 = tx * 4, r0 = ty * 4;
    unsigned long long acc[4][2];
    mm_tile(Ws, Xs, c0, r0, acc);

#pragma unroll
    for (int i = 0; i < 4; i++) {
        int r = rowBase + r0 + i;
        if (r < N) {
            float dv = g_dinv[r];
            float a0, a1, a2, a3;
            UNPACK2(a0, a1, acc[i][0]);
            UNPACK2(a2, a3, acc[i][1]);
            float4 o = make_float4(a0 * dv, a1 * dv, a2 * dv, a3 * dv);
            *(float4*)(g_hs    + (size_t)r * 128 + c0) = o;
            *(float4*)(aggout  + (size_t)r * 128 + c0) = o;  // self-loop seed
        }
    }
}

// ---------------- final GEMM: [mu|lv] = relu(dinv*aggB+b2) @ [Wmu|Wlv] + bias

__global__ void __launch_bounds__(256)
gemm_final_kernel(const float* __restrict__ Wmu,
                  const float* __restrict__ Wlv,
                  const float* __restrict__ bmu,
                  const float* __restrict__ blv,
                  const float* __restrict__ b2,
                  float* __restrict__ out,
                  int N) {
    extern __shared__ float sm[];
    float* Ws = sm;
    float* Xs = sm + 128 * 128;
    const int t = threadIdx.x;

#pragma unroll
    for (int i = 0; i < 16; i++) {
        int idx = t + i * 256;
        int k = idx >> 5;
        int cc4 = idx & 31;
        float4 v = (cc4 < 16) ? ((const float4*)Wmu)[k * 16 + cc4]
                              : ((const float4*)Wlv)[k * 16 + (cc4 - 16)];
        ((float4*)Ws)[idx] = v;
    }
    const int rowBase = blockIdx.x * 32;
    load_xtile(Xs, (const float*)g_aggB, b2, 1, rowBase, N, t);
    __syncthreads();

    const int tx = t & 31, ty = t >> 5;
    const int c0 = tx * 4, r0 = ty * 4;
    unsigned long long acc[4][2];
    mm_tile(Ws, Xs, c0, r0, acc);

    const bool is_mu = (c0 < 64);
    float4 bias = is_mu ? *(const float4*)(bmu + c0) : *(const float4*)(blv + (c0 - 64));
#pragma unroll
    for (int i = 0; i < 4; i++) {
        int r = rowBase + r0 + i;
        if (r < N) {
            float a0, a1, a2, a3;
            UNPACK2(a0, a1, acc[i][0]);
            UNPACK2(a2, a3, acc[i][1]);
            float4 o = make_float4(a0 + bias.x, a1 + bias.y, a2 + bias.z, a3 + bias.w);
            if (is_mu)
                *(float4*)(out + (size_t)r * 64 + c0) = o;
            else
                *(float4*)(out + (size_t)N * 64 + (size_t)r * 64 + (c0 - 64)) = o;
        }
    }
}

// ---------------- scatter: agg[dst] += hs[src] (one warp per edge) ----------

__device__ __forceinline__ void red_add_v4(float* p, float4 v) {
    asm volatile("red.global.add.v4.f32 [%0], {%1, %2, %3, %4};"
                 :: "l"(p), "f"(v.x), "f"(v.y), "f"(v.z), "f"(v.w)
                 : "memory");
}

__global__ void scatter_kernel(const int* __restrict__ ei, int E, int which) {
    int w = (blockIdx.x * blockDim.x + threadIdx.x) >> 5;
    int lane = threadIdx.x & 31;
    if (w >= E) return;
    float* agg = which ? g_aggB : g_aggA;
    int s = ei[w];
    int d = ei[E + w];
    float4 v = *(const float4*)(g_hs + (size_t)s * 128 + lane * 4);
    red_add_v4(agg + (size_t)d * 128 + lane * 4, v);
}

// ---------------- launch ----------------

extern "C" void kernel_launch(void* const* d_in, const int* in_sizes, int n_in,
                              void* d_out, int out_size) {
    const float* x   = (const float*)d_in[0];
    const int*   ei  = (const int*)d_in[1];      // int32 edge_index [2, E]
    const float* W1  = (const float*)d_in[2];
    const float* b1  = (const float*)d_in[3];
    const float* W2  = (const float*)d_in[4];
    const float* b2  = (const float*)d_in[5];
    const float* Wmu = (const float*)d_in[6];
    const float* bmu = (const float*)d_in[7];
    const float* Wlv = (const float*)d_in[8];
    const float* blv = (const float*)d_in[9];
    float* out = (float*)d_out;

    const int N = in_sizes[0] / 128;
    const int E = in_sizes[1] / 2;

    cudaFuncSetAttribute(gemm_conv_kernel,
                         cudaFuncAttributeMaxDynamicSharedMemorySize, GEMM_SMEM);
    cudaFuncSetAttribute(gemm_final_kernel,
                         cudaFuncAttributeMaxDynamicSharedMemorySize, GEMM_SMEM);

    const int gemm_blocks = (N + 31) / 32;
    const int scat_blocks = (E + 7) / 8;   // 8 warps/block, 1 warp/edge

    // degrees
    init_one_kernel<<<(N + 255) / 256, 256>>>(N);
    count_deg_kernel<<<(E + 255) / 256, 256>>>(ei, E);
    rsqrt_kernel<<<(N + 255) / 256, 256>>>(N);

    // conv1: x -> hs, aggA ; scatter into aggA
    gemm_conv_kernel<<<gemm_blocks, 256, GEMM_SMEM>>>(x, W1, b1 /*unused*/, N, 0);
    scatter_kernel<<<scat_blocks, 256>>>(ei, E, 0);

    // conv2: relu(dinv*aggA + b1) -> hs, aggB ; scatter into aggB
    gemm_conv_kernel<<<gemm_blocks, 256, GEMM_SMEM>>>(x, W2, b1, N, 1);
    scatter_kernel<<<scat_blocks, 256>>>(ei, E, 1);

    // heads: relu(dinv*aggB + b2) @ [Wmu|Wlv] + [bmu|blv]
    gemm_final_kernel<<<gemm_blocks, 256, GEMM_SMEM>>>(Wmu, Wlv, bmu, blv, b2, out, N);
}